// round 9
// baseline (speedup 1.0000x reference)
#include <cuda_runtime.h>
#include <cstdint>

// FinePreprocess: gather 5x5 windows (stride 4, pad 2) from two NCHW f32
// feature maps at per-match window indices. Output = concat[(M,25,C) f0,
// (M,25,C) f1]; per-match flat layout is c*25 + wy*5 + wx.
//
// R9: 4 patches per block, double-buffered smem, software pipeline:
//   iter k: STS(patch k, buf) ; bar ; LDG(patch k+1 -> regs) ; writeout(buf)
// LDGs for k+1 overlap the coalesced STG.128 writeout of k.

#define FP_N 4
#define FP_C 128
#define FP_H 240
#define FP_W 320
#define FP_OUTW 80
#define FP_L 4800            // 60*80
#define PATCH_WORDS 3200     // C*25
#define PATCH_VEC4 800
#define PPB 4                // patches per block

__device__ __forceinline__ void load_patch(
    int p, int M, int wy, int c,
    const float* __restrict__ feat0, const float* __restrict__ feat1,
    const int* __restrict__ b_ids, const int* __restrict__ i_ids,
    const int* __restrict__ j_ids,
    float4& A, float4& B)
{
    A = make_float4(0.f, 0.f, 0.f, 0.f);
    B = make_float4(0.f, 0.f, 0.f, 0.f);
    if (p >= 2 * M) return;
    int f = p >= M;
    int m = f ? p - M : p;

    int b   = min(max(b_ids[m], 0), FP_N - 1);
    int idx = min(max((f ? j_ids : i_ids)[m], 0), FP_L - 1);
    int gy  = idx / FP_OUTW;
    int gx  = idx - gy * FP_OUTW;
    int h   = gy * 4 + wy - 2;

    if (h >= 0 && h < FP_H) {
        const float* __restrict__ src = f ? feat1 : feat0;
        const float4* __restrict__ row4 = (const float4*)
            (src + (((long long)b * FP_C + c) * FP_H + h) * FP_W);
        if (gx > 0)                      // block-uniform branch
            A = __ldg(row4 + (gx - 1));  // elements 4gx-4 .. 4gx-1
        B = __ldg(row4 + gx);            // elements 4gx   .. 4gx+3
    }
    // window = elements 4gx-2 .. 4gx+2 -> {A.z, A.w, B.x, B.y, B.z}
}

__global__ void __launch_bounds__(640, 3)
fine_gather_kernel(const float* __restrict__ feat0,
                   const float* __restrict__ feat1,
                   const int* __restrict__ b_ids,
                   const int* __restrict__ i_ids,
                   const int* __restrict__ j_ids,
                   float* __restrict__ out,
                   int M)
{
    __shared__ float s[2][PATCH_WORDS];

    int tid  = threadIdx.x;            // 0..639 == c*5 + wy
    int c    = tid / 5;
    int wy   = tid - 5 * c;
    int base = blockIdx.x * PPB;

    float4 A, B;
    load_patch(base, M, wy, c, feat0, feat1, b_ids, i_ids, j_ids, A, B);

    int buf = 0;
#pragma unroll
    for (int k = 0; k < PPB; k++) {
        int p = base + k;

        // stage patch p into smem in final output order (word 5*tid)
        float* __restrict__ srow = s[buf] + tid * 5;
        srow[0] = A.z;
        srow[1] = A.w;
        srow[2] = B.x;
        srow[3] = B.y;
        srow[4] = B.z;
        __syncthreads();

        // kick off next patch's gathers; latency hides under the writeout
        if (k + 1 < PPB)
            load_patch(p + 1, M, wy, c, feat0, feat1, b_ids, i_ids, j_ids, A, B);

        if (p < 2 * M) {
            float4* __restrict__ out4 = (float4*)out + (long long)p * PATCH_VEC4;
            const float4* __restrict__ s4 = (const float4*)s[buf];
            out4[tid] = s4[tid];
            if (tid < PATCH_VEC4 - 640)
                out4[640 + tid] = s4[640 + tid];
        }
        buf ^= 1;
        // no second barrier: next STS into this buffer happens at iter k+2,
        // after the bar at iter k+1 -> all LDS of this buffer have drained.
    }
}

extern "C" void kernel_launch(void* const* d_in, const int* in_sizes, int n_in,
                              void* d_out, int out_size)
{
    // metadata order: feat_f0, feat_f1, hw0_f, hw0_c, b_ids, i_ids, j_ids
    const float* feat0 = (const float*)d_in[0];
    const float* feat1 = (const float*)d_in[1];
    const int*   b_ids = (const int*)d_in[4];
    const int*   i_ids = (const int*)d_in[5];
    const int*   j_ids = (const int*)d_in[6];
    float* out = (float*)d_out;

    int M = in_sizes[4];   // 6000

    int patches = 2 * M;
    int blocks  = (patches + PPB - 1) / PPB;   // 3000 for M=6000
    fine_gather_kernel<<<blocks, 640>>>(feat0, feat1, b_ids, i_ids, j_ids, out, M);
}